// round 2
// baseline (speedup 1.0000x reference)
#include <cuda_runtime.h>
#include <cstdint>

#define T_DIM 1024
#define CH 64
#define BT 128
#define BS 64
#define KS_STRIDE 72
#define VS_STRIDE 72
#define MS_STRIDE 68
#define NEG_INF (__int_as_float(0xff800000))

__device__ __forceinline__ uint32_t f2tf(float f) {
    uint32_t r;
    asm("cvt.rna.tf32.f32 %0, %1;" : "=r"(r) : "f"(f));
    return r;
}

__device__ __forceinline__ void mma_tf32(float d[4], const uint32_t a[4],
                                         uint32_t b0, uint32_t b1) {
    asm volatile(
        "mma.sync.aligned.m16n8k8.row.col.f32.tf32.tf32.f32 "
        "{%0,%1,%2,%3}, {%4,%5,%6,%7}, {%8,%9}, {%0,%1,%2,%3};\n"
        : "+f"(d[0]), "+f"(d[1]), "+f"(d[2]), "+f"(d[3])
        : "r"(a[0]), "r"(a[1]), "r"(a[2]), "r"(a[3]), "r"(b0), "r"(b1));
}

__global__ __launch_bounds__(256, 1) void attn_flash_kernel(
    const float* __restrict__ qkv,
    const int* __restrict__ mask,
    const float* __restrict__ qk_bias,
    float* __restrict__ out)
{
    __shared__ __align__(16) uint32_t Ks[CH * KS_STRIDE];
    __shared__ __align__(16) uint32_t Vs[CH * VS_STRIDE];
    __shared__ __align__(16) unsigned char Ms[BT * MS_STRIDE];

    const int tile_t = blockIdx.x;   // 0..7  (t tile of 128)
    const int bh = blockIdx.y;       // 0..127 (b*16 + h)
    const int tid = threadIdx.x;
    const int wid = tid >> 5;
    const int lane = tid & 31;
    const int g = lane >> 2;     // row group 0..7
    const int m4 = lane & 3;     // thread-in-group 0..3

    // qkv layout: [bs][3072][1024]; head block of 192 channels: q(0:64) k(64:128) v(128:192)
    const float* qp = qkv + (size_t)bh * 192 * T_DIM;
    const float* kp = qp + CH * T_DIM;
    const float* vp = qp + 2 * CH * T_DIM;
    // jnp.tile(mask,(16,1,1)) => mask index (b*16+h) % 8 == bh % 8
    const int* mp = mask + (size_t)(bh & 7) * T_DIM * T_DIM;

    const int t0c = tile_t * BT;
    const int t0 = t0c + wid * 16;
    const float bias2 = qk_bias[0] * 1.4426950408889634f;       // bias in log2 domain
    const float scale2 = 0.125f * 1.4426950408889634f;          // (1/sqrt(64)) * log2(e)

    // Q fragments (A-regs for S-mma), loaded once, held in regs: qf[k][0..3]
    uint32_t qf[8][4];
    #pragma unroll
    for (int k = 0; k < 8; k++) {
        const float* q0 = qp + (8 * k + m4) * T_DIM + t0 + g;
        const float* q1 = qp + (8 * k + m4 + 4) * T_DIM + t0 + g;
        qf[k][0] = f2tf(q0[0]);
        qf[k][1] = f2tf(q0[8]);
        qf[k][2] = f2tf(q1[0]);
        qf[k][3] = f2tf(q1[8]);
    }

    float o[8][4];
    #pragma unroll
    for (int n = 0; n < 8; n++) { o[n][0] = 0.f; o[n][1] = 0.f; o[n][2] = 0.f; o[n][3] = 0.f; }
    float mr0 = NEG_INF, mr1 = NEG_INF, lr0 = 0.f, lr1 = 0.f;

    for (int st = 0; st < 16; st++) {
        const int s0 = st * BS;

        // --- stage K,V tiles [64ch x 64s] (tf32-converted), mask tile [128t x 64s] ---
        #pragma unroll
        for (int it = 0; it < 4; it++) {
            int fid = tid + it * 256;           // 0..1023 float4s
            int c = fid >> 4;
            int s4 = (fid & 15) << 2;
            float4 k4 = *(const float4*)(kp + c * T_DIM + s0 + s4);
            uint32_t* kd = &Ks[c * KS_STRIDE + s4];
            kd[0] = f2tf(k4.x); kd[1] = f2tf(k4.y); kd[2] = f2tf(k4.z); kd[3] = f2tf(k4.w);
            float4 v4 = *(const float4*)(vp + c * T_DIM + s0 + s4);
            uint32_t* vd = &Vs[c * VS_STRIDE + s4];
            vd[0] = f2tf(v4.x); vd[1] = f2tf(v4.y); vd[2] = f2tf(v4.z); vd[3] = f2tf(v4.w);
        }
        // mask is int32 (bool normalized by harness): int4 load, pack to bytes
        #pragma unroll
        for (int it = 0; it < 8; it++) {
            int idx = tid + it * 256;           // 0..2047 groups of 4 ints
            int r = idx >> 4;
            int w = (idx & 15) << 2;
            int4 mw = *(const int4*)(mp + (size_t)(t0c + r) * T_DIM + s0 + w);
            unsigned char* md = &Ms[r * MS_STRIDE + w];
            md[0] = (unsigned char)mw.x;
            md[1] = (unsigned char)mw.y;
            md[2] = (unsigned char)mw.z;
            md[3] = (unsigned char)mw.w;
        }
        __syncthreads();

        // --- S = Q^T K for this warp's 16 rows x 64 cols ---
        float sacc[8][4];
        #pragma unroll
        for (int n = 0; n < 8; n++) { sacc[n][0]=0.f; sacc[n][1]=0.f; sacc[n][2]=0.f; sacc[n][3]=0.f; }
        #pragma unroll
        for (int k = 0; k < 8; k++) {
            const uint32_t* krow0 = &Ks[(8 * k + m4) * KS_STRIDE];
            const uint32_t* krow1 = krow0 + 4 * KS_STRIDE;
            #pragma unroll
            for (int n = 0; n < 8; n++) {
                mma_tf32(sacc[n], qf[k], krow0[8 * n + g], krow1[8 * n + g]);
            }
        }

        // --- mask + online softmax (log2 domain) ---
        float tmax0 = NEG_INF, tmax1 = NEG_INF;
        const unsigned char* mrow_lo = &Ms[(wid * 16 + g) * MS_STRIDE + 2 * m4];
        const unsigned char* mrow_hi = mrow_lo + 8 * MS_STRIDE;
        #pragma unroll
        for (int n = 0; n < 8; n++) {
            float v00 = mrow_lo[8*n]     ? fmaf(sacc[n][0], scale2, bias2) : NEG_INF;
            float v01 = mrow_lo[8*n + 1] ? fmaf(sacc[n][1], scale2, bias2) : NEG_INF;
            float v10 = mrow_hi[8*n]     ? fmaf(sacc[n][2], scale2, bias2) : NEG_INF;
            float v11 = mrow_hi[8*n + 1] ? fmaf(sacc[n][3], scale2, bias2) : NEG_INF;
            sacc[n][0] = v00; sacc[n][1] = v01; sacc[n][2] = v10; sacc[n][3] = v11;
            tmax0 = fmaxf(tmax0, fmaxf(v00, v01));
            tmax1 = fmaxf(tmax1, fmaxf(v10, v11));
        }
        tmax0 = fmaxf(tmax0, __shfl_xor_sync(0xffffffffu, tmax0, 1));
        tmax0 = fmaxf(tmax0, __shfl_xor_sync(0xffffffffu, tmax0, 2));
        tmax1 = fmaxf(tmax1, __shfl_xor_sync(0xffffffffu, tmax1, 1));
        tmax1 = fmaxf(tmax1, __shfl_xor_sync(0xffffffffu, tmax1, 2));

        float mn0 = fmaxf(mr0, tmax0);
        float mn1 = fmaxf(mr1, tmax1);
        float cor0 = exp2f(mr0 - mn0);
        float cor1 = exp2f(mr1 - mn1);
        mr0 = mn0; mr1 = mn1;

        float ps0 = 0.f, ps1 = 0.f;
        #pragma unroll
        for (int n = 0; n < 8; n++) {
            float p00 = exp2f(sacc[n][0] - mn0);
            float p01 = exp2f(sacc[n][1] - mn0);
            float p10 = exp2f(sacc[n][2] - mn1);
            float p11 = exp2f(sacc[n][3] - mn1);
            ps0 += p00 + p01;
            ps1 += p10 + p11;
            sacc[n][0] = __uint_as_float(f2tf(p00));
            sacc[n][1] = __uint_as_float(f2tf(p01));
            sacc[n][2] = __uint_as_float(f2tf(p10));
            sacc[n][3] = __uint_as_float(f2tf(p11));
        }
        ps0 += __shfl_xor_sync(0xffffffffu, ps0, 1);
        ps0 += __shfl_xor_sync(0xffffffffu, ps0, 2);
        ps1 += __shfl_xor_sync(0xffffffffu, ps1, 1);
        ps1 += __shfl_xor_sync(0xffffffffu, ps1, 2);
        lr0 = lr0 * cor0 + ps0;
        lr1 = lr1 * cor1 + ps1;

        #pragma unroll
        for (int n = 0; n < 8; n++) {
            o[n][0] *= cor0; o[n][1] *= cor0;
            o[n][2] *= cor1; o[n][3] *= cor1;
        }

        // --- O += P V^T. k-slot permutation: slot m <-> s = 8k+2m, slot m+4 <-> s = 8k+2m+1
        // makes A = sacc regs directly and B a vectorized uint2 load from Vs. ---
        #pragma unroll
        for (int k = 0; k < 8; k++) {
            uint32_t a[4];
            a[0] = __float_as_uint(sacc[k][0]);
            a[1] = __float_as_uint(sacc[k][2]);
            a[2] = __float_as_uint(sacc[k][1]);
            a[3] = __float_as_uint(sacc[k][3]);
            #pragma unroll
            for (int n = 0; n < 8; n++) {
                const uint32_t* vptr = &Vs[(8 * n + g) * VS_STRIDE + 8 * k + 2 * m4];
                uint2 b = *(const uint2*)vptr;
                mma_tf32(o[n], a, b.x, b.y);
            }
        }
        __syncthreads();
    }

    // --- normalize + write out[bh*64 + c][t] ---
    float il0 = 1.f / lr0;
    float il1 = 1.f / lr1;
    float* ob = out + (size_t)bh * 64 * T_DIM;
    #pragma unroll
    for (int n = 0; n < 8; n++) {
        int c = 8 * n + 2 * m4;
        ob[(size_t)c       * T_DIM + t0 + g]     = o[n][0] * il0;
        ob[(size_t)(c + 1) * T_DIM + t0 + g]     = o[n][1] * il0;
        ob[(size_t)c       * T_DIM + t0 + g + 8] = o[n][2] * il1;
        ob[(size_t)(c + 1) * T_DIM + t0 + g + 8] = o[n][3] * il1;
    }
}

extern "C" void kernel_launch(void* const* d_in, const int* in_sizes, int n_in,
                              void* d_out, int out_size) {
    const float* qkv = (const float*)d_in[0];
    const int* mask = (const int*)d_in[1];
    const float* bias = (const float*)d_in[2];
    float* out = (float*)d_out;
    dim3 grid(T_DIM / BT, 8 * 16);   // 8 t-tiles x 128 batch-heads
    attn_flash_kernel<<<grid, 256>>>(qkv, mask, bias, out);
}